// round 4
// baseline (speedup 1.0000x reference)
#include <cuda_runtime.h>
#include <cuda_fp16.h>
#include <cuda_fp8.h>
#include <math.h>
#include <stdint.h>

#define NS 305
#define SP 320
#define SPSP (SP * SP)
#define NB 64
#define NT 4096
#define NTAU 1023            // 4-gram steps (t=1..4092)
#define NSTEP (NTAU + 2)     // + Q-step + A-step
#define LOG_SCALE_D 8.317766166719343   // log(4096)
#define DITH1 1.0471f        // dither factor for copy 1 (compensated exactly via g_rs)

// ---------------- device globals (zero-initialized) ----------------
__device__ float g_I[SP];
__device__ __align__(16) float g_BmT[4][SP];              // BmT[a][s] = Bm[s][a]
__device__ __align__(16) float g_A32[SPSP];
__device__ __align__(16) float g_Q32[4][SPSP];
__device__ __align__(16) float g_R32[64 * SPSP];          // fp32 R_{abc}
__device__ __align__(16) unsigned char g_S[2 * 69 * SPSP]; // e5m2, 2 dither copies: 64 R, 4 Q, 1 A
__device__ __align__(16) float g_rs[2 * 69 * SP];         // alpha row multiplier 4096/q per copy
__device__ unsigned char g_gram[NB * NTAU];
__device__ unsigned char g_o0[NB];
__device__ unsigned char g_tail[NB];

__device__ __forceinline__ float warpSum(float x) {
    #pragma unroll
    for (int o = 16; o; o >>= 1) x += __shfl_down_sync(0xffffffffu, x, o);
    return x;
}
__device__ __forceinline__ float warpMax(float x) {
    #pragma unroll
    for (int o = 16; o; o >>= 1) x = fmaxf(x, __shfl_down_sync(0xffffffffu, x, o));
    return x;
}

__device__ __forceinline__ __half2 u2h(uint32_t u) { return *reinterpret_cast<__half2*>(&u); }
__device__ __forceinline__ uint32_t h2u(__half2 h) { return *reinterpret_cast<uint32_t*>(&h); }

#define BAR_SYNC(id, n)   asm volatile("bar.sync %0, %1;"   :: "n"(id), "n"(n) : "memory")
#define BAR_ARRIVE(id, n) asm volatile("bar.arrive %0, %1;" :: "n"(id), "n"(n) : "memory")

// ---------------- setup: I softmax + emission softmax ----------------
__global__ void k_setup(const float* __restrict__ initk, const float* __restrict__ emisk) {
    __shared__ float red[16];
    __shared__ float bval;
    int tid = threadIdx.x, wid = tid >> 5, lane = tid & 31;
    const int nw = 16;
    float v = (tid < NS) ? initk[tid] : -1e30f;
    float m = warpMax(v);
    if (lane == 0) red[wid] = m;
    __syncthreads();
    if (tid == 0) { float mm = -1e30f; for (int w = 0; w < nw; w++) mm = fmaxf(mm, red[w]); bval = mm; }
    __syncthreads();
    m = bval;
    float e = (tid < NS) ? expf(v - m) : 0.f;
    float s = warpSum(e);
    __syncthreads();
    if (lane == 0) red[wid] = s;
    __syncthreads();
    if (tid == 0) { float ss = 0.f; for (int w = 0; w < nw; w++) ss += red[w]; bval = ss; }
    __syncthreads();
    if (tid < NS) g_I[tid] = e / bval;

    if (tid < NS) {
        float x0 = emisk[tid * 4 + 0], x1 = emisk[tid * 4 + 1];
        float x2 = emisk[tid * 4 + 2], x3 = emisk[tid * 4 + 3];
        float mm = fmaxf(fmaxf(x0, x1), fmaxf(x2, x3));
        float e0 = expf(x0 - mm), e1 = expf(x1 - mm), e2 = expf(x2 - mm), e3 = expf(x3 - mm);
        float inv = 1.f / (e0 + e1 + e2 + e3);
        g_BmT[0][tid] = e0 * inv; g_BmT[1][tid] = e1 * inv;
        g_BmT[2][tid] = e2 * inv; g_BmT[3][tid] = e3 * inv;
    }
}

// ---------------- softmax rows of transition -> A32 ----------------
__global__ void k_softA(const float* __restrict__ trans) {
    __shared__ float red[10];
    __shared__ float bval;
    int r = blockIdx.x, tid = threadIdx.x;
    int wid = tid >> 5, lane = tid & 31;
    float v = (tid < NS) ? trans[r * NS + tid] : -1e30f;
    float m = warpMax(v);
    if (lane == 0) red[wid] = m;
    __syncthreads();
    if (tid == 0) { float mm = -1e30f; for (int w = 0; w < 10; w++) mm = fmaxf(mm, red[w]); bval = mm; }
    __syncthreads();
    m = bval;
    float e = (tid < NS) ? expf(v - m) : 0.f;
    float s = warpSum(e);
    __syncthreads();
    if (lane == 0) red[wid] = s;
    __syncthreads();
    if (tid == 0) { float ss = 0.f; for (int w = 0; w < 10; w++) ss += red[w]; bval = ss; }
    __syncthreads();
    if (tid < NS) g_A32[r * SP + tid] = e / bval;
}

// ---------------- observation -> gram indices ----------------
__global__ void k_gram(const float* __restrict__ inputs) {
    int b = blockIdx.x;
    const float* inb = inputs + (size_t)b * NT * 4;
    for (int tau = threadIdx.x; tau < NTAU; tau += blockDim.x) {
        int t0 = 1 + 4 * tau;
        unsigned g = 0;
        #pragma unroll
        for (int k = 0; k < 4; k++) {
            const float* p = inb + (size_t)(t0 + k) * 4;
            float fi = p[1] + 2.f * p[2] + 3.f * p[3];
            g = (g << 2) | (unsigned)(fi + 0.5f);
        }
        g_gram[b * NTAU + tau] = (unsigned char)g;
    }
    if (threadIdx.x == 0) {
        const float* p = inb;
        g_o0[b] = (unsigned char)(p[1] + 2.f * p[2] + 3.f * p[3] + 0.5f);
        unsigned tg = 0;
        #pragma unroll
        for (int k = 0; k < 3; k++) {
            const float* q = inb + (size_t)(4093 + k) * 4;
            tg = (tg << 2) | (unsigned)(q[1] + 2.f * q[2] + 3.f * q[3] + 0.5f);
        }
        g_tail[b] = (unsigned char)tg;
    }
}

// ---------------- fp32 GEMM with k-dim column scaling ----------------
// mode 0: Q_z = (A*D_z) @ A ; mode 1: R_z = (Q_a*D_b) @ Q_c
__global__ void __launch_bounds__(256) k_gemm(int mode) {
    int z = blockIdx.z;
    const float *Lp, *Rp, *sc;
    float* outf;
    if (mode == 0) {
        Lp = g_A32; Rp = g_A32; sc = g_BmT[z]; outf = g_Q32[z];
    } else {
        int a = z >> 4, bb = (z >> 2) & 3, c = z & 3;
        Lp = g_Q32[a]; sc = g_BmT[bb]; Rp = g_Q32[c]; outf = g_R32 + (size_t)z * SPSP;
    }
    int m0 = blockIdx.y * 64, n0 = blockIdx.x * 64;
    __shared__ __align__(16) float Ls[16][64];
    __shared__ __align__(16) float Rs[16][64];
    int tid = threadIdx.x;
    int tx = tid & 15, ty = tid >> 4;
    int lrow = tid >> 2, lk = (tid & 3) * 4;
    int rk = tid >> 4, rn = (tid & 15) * 4;

    float acc[4][4] = {};
    for (int k0 = 0; k0 < SP; k0 += 16) {
        float4 lv = *(const float4*)&Lp[(size_t)(m0 + lrow) * SP + k0 + lk];
        Ls[lk + 0][lrow] = lv.x * sc[k0 + lk + 0];
        Ls[lk + 1][lrow] = lv.y * sc[k0 + lk + 1];
        Ls[lk + 2][lrow] = lv.z * sc[k0 + lk + 2];
        Ls[lk + 3][lrow] = lv.w * sc[k0 + lk + 3];
        *(float4*)&Rs[rk][rn] = *(const float4*)&Rp[(size_t)(k0 + rk) * SP + n0 + rn];
        __syncthreads();
        #pragma unroll
        for (int kk = 0; kk < 16; kk++) {
            float4 av = *(const float4*)&Ls[kk][ty * 4];      // LDS.128
            float4 bv = *(const float4*)&Rs[kk][tx * 4];      // LDS.128
            acc[0][0] = fmaf(av.x, bv.x, acc[0][0]); acc[0][1] = fmaf(av.x, bv.y, acc[0][1]);
            acc[0][2] = fmaf(av.x, bv.z, acc[0][2]); acc[0][3] = fmaf(av.x, bv.w, acc[0][3]);
            acc[1][0] = fmaf(av.y, bv.x, acc[1][0]); acc[1][1] = fmaf(av.y, bv.y, acc[1][1]);
            acc[1][2] = fmaf(av.y, bv.z, acc[1][2]); acc[1][3] = fmaf(av.y, bv.w, acc[1][3]);
            acc[2][0] = fmaf(av.z, bv.x, acc[2][0]); acc[2][1] = fmaf(av.z, bv.y, acc[2][1]);
            acc[2][2] = fmaf(av.z, bv.z, acc[2][2]); acc[2][3] = fmaf(av.z, bv.w, acc[2][3]);
            acc[3][0] = fmaf(av.w, bv.x, acc[3][0]); acc[3][1] = fmaf(av.w, bv.y, acc[3][1]);
            acc[3][2] = fmaf(av.w, bv.z, acc[3][2]); acc[3][3] = fmaf(av.w, bv.w, acc[3][3]);
        }
        __syncthreads();
    }
    #pragma unroll
    for (int i = 0; i < 4; i++)
        #pragma unroll
        for (int j = 0; j < 4; j++)
            outf[(size_t)(m0 + ty * 4 + i) * SP + (n0 + tx * 4 + j)] = acc[i][j];
}

// ---------------- quantize to e5m2 with per-row scale, 2 dithered copies ----------------
__global__ void k_quant() {
    int r = blockIdx.x, z = blockIdx.y, c = blockIdx.z, tid = threadIdx.x;
    const float* src;
    if (z < 64) src = g_R32 + (size_t)z * SPSP;
    else if (z < 68) src = g_Q32[z - 64];
    else src = g_A32;
    float v = src[(size_t)r * SP + tid];
    __shared__ float red[10];
    __shared__ float bmax;
    int wid = tid >> 5, lane = tid & 31;
    float m = warpMax(v);
    if (lane == 0) red[wid] = m;
    __syncthreads();
    if (tid == 0) { float x = red[0]; for (int w = 1; w < 10; w++) x = fmaxf(x, red[w]); bmax = x; }
    __syncthreads();
    float mx = bmax;
    float q = (mx > 0.f) ? 384.f / mx : 1.f;
    if (c == 1) q *= DITH1;     // shift rounding grid; exactly compensated in g_rs
    g_S[((size_t)c * 69 + z) * SPSP + (size_t)r * SP + tid] =
        (unsigned char)__nv_cvt_float_to_fp8(v * q, __NV_SATFINITE, __NV_E5M2);
    if (tid == 0) g_rs[(c * 69 + z) * SP + r] = 4096.f / q;
}

// ---------------- chain: persistent CTA per batch, pipelined e5m2 matvec ----------------
// 640 threads. Thread: cp=tid%20 -> cols [16cp..16cp+15]; iq=tid/20 -> rows iq+32k (k<10).
// e5m2 -> f16 is PRMT-only: f16 = byte<<8 (bit-exact).
__global__ void __launch_bounds__(640, 1) k_chain(float* __restrict__ out) {
    int b = blockIdx.x, tid = threadIdx.x;
    __shared__ uint32_t part[2][32][160];
    __shared__ __half2 ah2[SP];
    __shared__ float redp[20];
    __shared__ float s_sinv;
    __shared__ unsigned char sg[NTAU + 1];
    int lane = tid & 31, wid = tid >> 5;
    int iq = tid / 20;
    int cp = tid % 20;

    for (int i = tid; i < NTAU; i += 640) sg[i] = g_gram[b * NTAU + i];
    unsigned tg = g_tail[b];
    int o0 = g_o0[b];
    __syncthreads();
    int z0 = sg[0] >> 2;

    // ---- prologue: alpha0 = normalize(I * Bm[:,o0]) ----
    double ll = 0.0;
    float v0p = (tid < SP) ? g_I[tid] * g_BmT[o0][tid] : 0.f;
    float wsum = warpSum(v0p);
    if (lane == 0) redp[wid] = wsum;
    __syncthreads();
    if (tid == 0) {
        float x = 0.f;
        #pragma unroll
        for (int w = 0; w < 20; w++) x += redp[w];
        s_sinv = 1.f / x;
        ll = (double)logf(x);
    }
    __syncthreads();
    float* af = (float*)&part[0][0][0];
    if (tid < SP) af[tid] = v0p * s_sinv;
    __syncthreads();
    if (tid < 160) {
        float2 rsv = *(const float2*)&g_rs[z0 * SP + 2 * tid];   // step 0 uses copy 0
        float a0 = af[2 * tid] * rsv.x, a1 = af[2 * tid + 1] * rsv.y;
        ah2[2 * tid]     = __floats2half2_rn(a0, a0);
        ah2[2 * tid + 1] = __floats2half2_rn(a1, a1);
    }
    __syncthreads();

    // ---- preload matrix regs for step 0 (copy 0) ----
    uint4 mr[10];
    {
        const uint4* p = (const uint4*)(g_S + (size_t)z0 * SPSP) + tid;
        #pragma unroll
        for (int k = 0; k < 10; k++) mr[k] = __ldcg(p + k * 640);
    }

    for (int step = 0; step < NSTEP; ++step) {
        int pb = step & 1;
        int d, zn;
        if (step < NTAU) d = sg[step] & 3;
        else if (step == NTAU) d = (tg >> 2) & 3;
        else d = tg & 3;
        if (step + 1 < NTAU) zn = sg[step + 1] >> 2;
        else if (step + 1 == NTAU) zn = 64 + ((tg >> 4) & 3);
        else zn = 68;
        int cn = (step + 1) & 1;                 // dither copy for NEXT step
        int zoff = cn * 69 + zn;

        // ---- FMA phase (all threads): e5m2 -> f16 via PRMT, HFMA2 accumulate ----
        __half2 a0 = __floats2half2_rn(0.f, 0.f);
        __half2 a1 = a0, a2 = a0, a3 = a0, a4 = a0, a5 = a0, a6 = a0, a7 = a0;
        #pragma unroll
        for (int k = 0; k < 10; k++) {
            __half2 av = ah2[iq + 32 * k];
            a0 = __hfma2(av, u2h(__byte_perm(mr[k].x, 0, 0x1404)), a0);
            a1 = __hfma2(av, u2h(__byte_perm(mr[k].x, 0, 0x3424)), a1);
            a2 = __hfma2(av, u2h(__byte_perm(mr[k].y, 0, 0x1404)), a2);
            a3 = __hfma2(av, u2h(__byte_perm(mr[k].y, 0, 0x3424)), a3);
            a4 = __hfma2(av, u2h(__byte_perm(mr[k].z, 0, 0x1404)), a4);
            a5 = __hfma2(av, u2h(__byte_perm(mr[k].z, 0, 0x3424)), a5);
            a6 = __hfma2(av, u2h(__byte_perm(mr[k].w, 0, 0x1404)), a6);
            a7 = __hfma2(av, u2h(__byte_perm(mr[k].w, 0, 0x3424)), a7);
        }
        uint32_t* dst = &part[pb][iq][cp * 8];
        *(uint4*)dst       = make_uint4(h2u(a0), h2u(a1), h2u(a2), h2u(a3));
        *(uint4*)(dst + 4) = make_uint4(h2u(a4), h2u(a5), h2u(a6), h2u(a7));

        if (tid < 160) {
            float2 rsv = *(const float2*)&g_rs[zoff * SP + 2 * tid];  // prefetch next scales
            BAR_SYNC(1, 640);                       // partials ready
            __half2 s2 = __floats2half2_rn(0.f, 0.f);
            #pragma unroll
            for (int k = 0; k < 32; k++)
                s2 = __hadd2(s2, *(const __half2*)&part[pb][k][tid]);
            float2 f2 = __half22float2(s2);
            float2 fo = *(const float2*)&g_BmT[d][2 * tid];
            float v0 = f2.x * fo.x, v1 = f2.y * fo.y;
            float t = warpSum(v0 + v1);
            if (lane == 0) redp[wid] = t;
            BAR_SYNC(3, 160);
            float stot = 0.f;
            if (wid == 0) {
                float x = (lane < 5) ? redp[lane] : 0.f;
                x = warpSum(x);
                if (lane == 0) { s_sinv = 1.f / x; stot = x; }
            }
            BAR_SYNC(3, 160);
            float si = s_sinv;
            float b0 = v0 * si * rsv.x, b1 = v1 * si * rsv.y;
            ah2[2 * tid]     = __floats2half2_rn(b0, b0);
            ah2[2 * tid + 1] = __floats2half2_rn(b1, b1);
            BAR_ARRIVE(2, 640);                     // alpha ready
            if (tid == 0) ll += (double)logf(stot);
        } else {
            BAR_ARRIVE(1, 640);
        }

        // ---- issue next step's loads (alternating dither copy) ----
        {
            const uint4* p = (const uint4*)(g_S + (size_t)zoff * SPSP) + tid;
            #pragma unroll
            for (int k = 0; k < 10; k++) mr[k] = __ldcg(p + k * 640);
        }
        if (tid >= 160) BAR_SYNC(2, 640);
    }
    if (tid == 0) out[b] = (float)(ll - (double)NSTEP * LOG_SCALE_D);
}

// ---------------- launch ----------------
extern "C" void kernel_launch(void* const* d_in, const int* in_sizes, int n_in,
                              void* d_out, int out_size) {
    const float* inputs = (const float*)d_in[0];
    const float* initk  = (const float*)d_in[1];
    const float* transk = (const float*)d_in[2];
    const float* emisk  = (const float*)d_in[3];
    float* out = (float*)d_out;

    k_setup<<<1, 512>>>(initk, emisk);
    k_softA<<<NS, 320>>>(transk);
    k_gram<<<NB, 256>>>(inputs);
    k_gemm<<<dim3(5, 5, 4), 256>>>(0);
    k_gemm<<<dim3(5, 5, 64), 256>>>(1);
    k_quant<<<dim3(320, 69, 2), 320>>>();
    k_chain<<<NB, 640>>>(out);
}